// round 14
// baseline (speedup 1.0000x reference)
#include <cuda_runtime.h>
#include <cuda_bf16.h>
#include <cstdint>

// Perceive3D: out[b, k*16+c, z, h, w], k in {identity, d/dW, d/dH, d/dD} (Sobel-smoothed, /16),
// replicate padding. Separable: s=[1,2,1], d=[-1,0,1].
//
// R14: R13 base with the identity-output rotation eliminated — ident(z) needs no
// z-window (it's just the center sample), so it is stored in the SAME iteration its
// plane is consumed. Saves 8 regs of rotation state; __launch_bounds__(128,8) forces
// <=64 regs -> 8 CTAs/SM -> 32 warps x 512B stored-bytes-in-flight (+50% vs R12/13's
// conserved 10.8KB/SM, which the register file was shown to bind).

#define ZLEN 8
#define HTB  8   // H rows per block = 4 warps x 2 rows

__global__ __launch_bounds__(128, 8)
void perceive3d_kernel(const float* __restrict__ x, float* __restrict__ out) {
    const int lx = threadIdx.x;            // 0..31 -> W pair (2lx, 2lx+1)
    const int ly = threadIdx.y;            // 0..3  -> warp; owns rows h, h+1
    const int h  = blockIdx.x * HTB + 2 * ly;
    const int bc = blockIdx.y;             // 0..63 = b*16+c
    const int z0 = blockIdx.z * ZLEN;
    const int b  = bc >> 4;
    const int c  = bc & 15;

    const size_t cstride = (size_t)64 * 64 * 64;
    const float* __restrict__ xin = x + (size_t)bc * cstride;
    float* __restrict__ out0 = out + ((size_t)(b * 64) + c) * cstride;

    const int hA = (h == 0) ? 0 : h - 1;       // h-1 clamped
    const int hD = (h + 2 > 63) ? 63 : h + 2;  // h+2 clamped
    const int col = 2 * lx;
    const float* __restrict__ rA = xin + hA * 64 + col;
    const float* __restrict__ rB = xin + (size_t)h * 64 + col;
    const float* __restrict__ rC = xin + (size_t)(h + 1) * 64 + col;
    const float* __restrict__ rD = xin + hD * 64 + col;
    const int line = h * 64 + col;             // row h; row h+1 = line + 64

    // load the 4 H rows of plane z (z-clamped) for this thread's W pair
    auto loadPlane = [&](int z, float2* v) {
        int zz = z < 0 ? 0 : (z > 63 ? 63 : z);
        const size_t off = (size_t)zz * 4096;
        v[0] = *(const float2*)(rA + off);
        v[1] = *(const float2*)(rB + off);
        v[2] = *(const float2*)(rC + off);
        v[3] = *(const float2*)(rD + off);
    };

    // plane stats for BOTH rows: row0 from (A,B,C), row1 from (B,C,D). No center kept.
    auto stats = [&](const float2* v, float2* P, float2* QW, float2* QH) {
        #pragma unroll
        for (int r = 0; r < 2; r++) {
            float2 vm = v[r], vc = v[r + 1], vp = v[r + 2];
            float2 sv, dv;
            sv.x = vm.x + 2.f * vc.x + vp.x;  sv.y = vm.y + 2.f * vc.y + vp.y;
            dv.x = vp.x - vm.x;               dv.y = vp.y - vm.y;
            float svL = __shfl_up_sync(0xffffffffu,  sv.y, 1);  // col-1
            float svR = __shfl_down_sync(0xffffffffu, sv.x, 1); // col+2
            float dvL = __shfl_up_sync(0xffffffffu,  dv.y, 1);
            float dvR = __shfl_down_sync(0xffffffffu, dv.x, 1);
            if (lx == 0)  { svL = sv.x; dvL = dv.x; }   // replicate at W=0
            if (lx == 31) { svR = sv.y; dvR = dv.y; }   // replicate at W=63
            P[r].x  = svL  + 2.f * sv.x + sv.y;   P[r].y  = sv.x + 2.f * sv.y + svR;
            QW[r].x = sv.y - svL;                 QW[r].y = svR  - sv.x;
            QH[r].x = dvL  + 2.f * dv.x + dv.y;   QH[r].y = dv.x + 2.f * dv.y + dvR;
        }
    };

    // store identity for plane z directly from its raw center rows (no rotation)
    auto emitIdent = [&](int z, const float2* v) {
        const size_t o = (size_t)z * 4096 + line;
        *(float2*)(out0 + o)      = v[1];
        *(float2*)(out0 + o + 64) = v[2];
    };

    // store the three derivative outputs for plane z
    auto emitDeriv = [&](int z, const float2* Pp, const float2* Pn,
                         const float2* Xp, const float2* Xc, const float2* Xn,
                         const float2* Yp, const float2* Yc, const float2* Yn) {
        const size_t o = (size_t)z * 4096 + line;
        #pragma unroll
        for (int r = 0; r < 2; r++) {
            float2 sx, sy, sz;
            sx.x = (Xp[r].x + 2.f * Xc[r].x + Xn[r].x) * 0.0625f;
            sx.y = (Xp[r].y + 2.f * Xc[r].y + Xn[r].y) * 0.0625f;
            sy.x = (Yp[r].x + 2.f * Yc[r].x + Yn[r].x) * 0.0625f;
            sy.y = (Yp[r].y + 2.f * Yc[r].y + Yn[r].y) * 0.0625f;
            sz.x = (Pn[r].x - Pp[r].x) * 0.0625f;
            sz.y = (Pn[r].y - Pp[r].y) * 0.0625f;
            const size_t orow = o + r * 64;
            *(float2*)(out0 + orow + 16 * cstride) = sx;
            *(float2*)(out0 + orow + 32 * cstride) = sy;
            *(float2*)(out0 + orow + 48 * cstride) = sz;
        }
    };

    float2 A[4], B[4];                      // raw plane double buffer (4 rows)
    float2 Pp[2], Pc[2], Pn[2];
    float2 Xp[2], Xc[2], Xn[2];
    float2 Yp[2], Yc[2], Yn[2];

    // prologue: plane z0-1 -> prev stats; plane z0 -> cur stats + its identity;
    // plane z0+1 staged in A.
    loadPlane(z0 - 1, A);
    stats(A, Pp, Xp, Yp);
    loadPlane(z0, A);
    stats(A, Pc, Xc, Yc);
    emitIdent(z0, A);
    loadPlane(z0 + 1, A);

    #pragma unroll
    for (int t = 0; t < ZLEN; t += 2) {
        // even step: prefetch z0+t+2 into B, consume A (= plane z0+t+1)
        if (t + 2 <= ZLEN) loadPlane(z0 + t + 2, B);
        stats(A, Pn, Xn, Yn);
        if (t + 1 < ZLEN) emitIdent(z0 + t + 1, A);       // ident of consumed plane
        emitDeriv(z0 + t, Pp, Pn, Xp, Xc, Xn, Yp, Yc, Yn);
        #pragma unroll
        for (int r = 0; r < 2; r++) {
            Pp[r] = Pc[r]; Pc[r] = Pn[r];
            Xp[r] = Xc[r]; Xc[r] = Xn[r];
            Yp[r] = Yc[r]; Yc[r] = Yn[r];
        }

        // odd step: prefetch z0+t+3 into A, consume B (= plane z0+t+2)
        if (t + 3 <= ZLEN) loadPlane(z0 + t + 3, A);
        stats(B, Pn, Xn, Yn);
        if (t + 2 < ZLEN) emitIdent(z0 + t + 2, B);
        emitDeriv(z0 + t + 1, Pp, Pn, Xp, Xc, Xn, Yp, Yc, Yn);
        #pragma unroll
        for (int r = 0; r < 2; r++) {
            Pp[r] = Pc[r]; Pc[r] = Pn[r];
            Xp[r] = Xc[r]; Xc[r] = Xn[r];
            Yp[r] = Yc[r]; Yc[r] = Yn[r];
        }
    }
}

extern "C" void kernel_launch(void* const* d_in, const int* in_sizes, int n_in,
                              void* d_out, int out_size) {
    const float* x = (const float*)d_in[0];
    // d_in[1] = kernels (4x3x3x3) — fixed separable stencils folded into the kernel.
    float* out = (float*)d_out;

    dim3 grid(64 / HTB, 64, 64 / ZLEN);  // (8 H tiles, B*C=64, 8 z chunks) = 4096 blocks
    dim3 block(32, 4);                   // 128 threads; warp = two H rows
    perceive3d_kernel<<<grid, block>>>(x, out);
}

// round 15
// speedup vs baseline: 1.0370x; 1.0370x over previous
#include <cuda_runtime.h>
#include <cuda_bf16.h>
#include <cstdint>

// Perceive3D: out[b, k*16+c, z, h, w], k in {identity, d/dW, d/dH, d/dD} (Sobel-smoothed, /16),
// replicate padding. Separable: s=[1,2,1], d=[-1,0,1].
//
// R15: R13 base (best wall 55.4us) with ZLEN 8->4 and guarded prefetch.
// Eight variants pinned DRAM at 63-68.6% across occ 33-66% — we are at the achievable
// write-bandwidth roofline (~5.4TB/s); the remaining recoverable time is the wave-tail:
// 4096 blocks / 888 slots = 4.6 waves (61%-full tail, ~8% waste) -> 8192 blocks = 9.2
// waves (~1% waste). Extra prologue plane reads are L2 hits (input L2-resident).

#define ZLEN 4
#define HTB  8   // H rows per block = 4 warps x 2 rows

__global__ __launch_bounds__(128, 6)
void perceive3d_kernel(const float* __restrict__ x, float* __restrict__ out) {
    const int lx = threadIdx.x;            // 0..31 -> W pair (2lx, 2lx+1)
    const int ly = threadIdx.y;            // 0..3  -> warp; owns rows h, h+1
    const int h  = blockIdx.x * HTB + 2 * ly;
    const int bc = blockIdx.y;             // 0..63 = b*16+c
    const int z0 = blockIdx.z * ZLEN;
    const int b  = bc >> 4;
    const int c  = bc & 15;

    const size_t cstride = (size_t)64 * 64 * 64;
    const float* __restrict__ xin = x + (size_t)bc * cstride;
    float* __restrict__ out0 = out + ((size_t)(b * 64) + c) * cstride;

    const int hA = (h == 0) ? 0 : h - 1;       // h-1 clamped
    const int hD = (h + 2 > 63) ? 63 : h + 2;  // h+2 clamped
    const int col = 2 * lx;
    const float* __restrict__ rA = xin + hA * 64 + col;
    const float* __restrict__ rB = xin + (size_t)h * 64 + col;
    const float* __restrict__ rC = xin + (size_t)(h + 1) * 64 + col;
    const float* __restrict__ rD = xin + hD * 64 + col;
    const int line = h * 64 + col;             // row h; row h+1 = line + 64

    // load the 4 H rows of plane z (z-clamped) for this thread's W pair
    auto loadPlane = [&](int z, float2* v) {
        int zz = z < 0 ? 0 : (z > 63 ? 63 : z);
        const size_t off = (size_t)zz * 4096;
        v[0] = *(const float2*)(rA + off);
        v[1] = *(const float2*)(rB + off);
        v[2] = *(const float2*)(rC + off);
        v[3] = *(const float2*)(rD + off);
    };

    // plane stats for BOTH rows: row0 from (A,B,C), row1 from (B,C,D).
    auto stats = [&](const float2* v, float2* P, float2* QW, float2* QH, float2* CC) {
        #pragma unroll
        for (int r = 0; r < 2; r++) {
            float2 vm = v[r], vc = v[r + 1], vp = v[r + 2];
            float2 sv, dv;
            sv.x = vm.x + 2.f * vc.x + vp.x;  sv.y = vm.y + 2.f * vc.y + vp.y;
            dv.x = vp.x - vm.x;               dv.y = vp.y - vm.y;
            float svL = __shfl_up_sync(0xffffffffu,  sv.y, 1);  // col-1
            float svR = __shfl_down_sync(0xffffffffu, sv.x, 1); // col+2
            float dvL = __shfl_up_sync(0xffffffffu,  dv.y, 1);
            float dvR = __shfl_down_sync(0xffffffffu, dv.x, 1);
            if (lx == 0)  { svL = sv.x; dvL = dv.x; }   // replicate at W=0
            if (lx == 31) { svR = sv.y; dvR = dv.y; }   // replicate at W=63
            P[r].x  = svL  + 2.f * sv.x + sv.y;   P[r].y  = sv.x + 2.f * sv.y + svR;
            QW[r].x = sv.y - svL;                 QW[r].y = svR  - sv.x;
            QH[r].x = dvL  + 2.f * dv.x + dv.y;   QH[r].y = dv.x + 2.f * dv.y + dvR;
            CC[r]   = vc;
        }
    };

    // emit all four outputs for both rows of plane z (write-back stores)
    auto emit = [&](int z, const float2* Pp, const float2* Pn,
                    const float2* Xp, const float2* Xc, const float2* Xn,
                    const float2* Yp, const float2* Yc, const float2* Yn,
                    const float2* Cc) {
        const size_t o = (size_t)z * 4096 + line;
        #pragma unroll
        for (int r = 0; r < 2; r++) {
            float2 sx, sy, sz;
            sx.x = (Xp[r].x + 2.f * Xc[r].x + Xn[r].x) * 0.0625f;
            sx.y = (Xp[r].y + 2.f * Xc[r].y + Xn[r].y) * 0.0625f;
            sy.x = (Yp[r].x + 2.f * Yc[r].x + Yn[r].x) * 0.0625f;
            sy.y = (Yp[r].y + 2.f * Yc[r].y + Yn[r].y) * 0.0625f;
            sz.x = (Pn[r].x - Pp[r].x) * 0.0625f;
            sz.y = (Pn[r].y - Pp[r].y) * 0.0625f;
            const size_t orow = o + r * 64;
            *(float2*)(out0 + orow)                = Cc[r];
            *(float2*)(out0 + orow + 16 * cstride) = sx;
            *(float2*)(out0 + orow + 32 * cstride) = sy;
            *(float2*)(out0 + orow + 48 * cstride) = sz;
        }
    };

    float2 A[4], B[4];                                   // raw plane double buffer (4 rows)
    float2 Pp[2], Pc[2], Pn[2];
    float2 Xp[2], Xc[2], Xn[2];
    float2 Yp[2], Yc[2], Yn[2];
    float2 Cc[2], Cn[2];

    // prologue: planes z0-1, z0 -> stats; plane z0+1 staged in A
    loadPlane(z0 - 1, A);
    stats(A, Pp, Xp, Yp, Cn);
    loadPlane(z0, A);
    stats(A, Pc, Xc, Yc, Cc);
    loadPlane(z0 + 1, A);

    #pragma unroll
    for (int t = 0; t < ZLEN; t += 2) {
        // even step: prefetch z+2 into B (guarded to needed range), consume A (= plane z+1)
        if (t + 2 <= ZLEN) loadPlane(z0 + t + 2, B);
        stats(A, Pn, Xn, Yn, Cn);
        emit(z0 + t, Pp, Pn, Xp, Xc, Xn, Yp, Yc, Yn, Cc);
        #pragma unroll
        for (int r = 0; r < 2; r++) {
            Pp[r] = Pc[r]; Pc[r] = Pn[r];
            Xp[r] = Xc[r]; Xc[r] = Xn[r];
            Yp[r] = Yc[r]; Yc[r] = Yn[r];
            Cc[r] = Cn[r];
        }

        // odd step: prefetch z+3 into A (guarded), consume B (= plane z+2)
        if (t + 3 <= ZLEN) loadPlane(z0 + t + 3, A);
        stats(B, Pn, Xn, Yn, Cn);
        emit(z0 + t + 1, Pp, Pn, Xp, Xc, Xn, Yp, Yc, Yn, Cc);
        #pragma unroll
        for (int r = 0; r < 2; r++) {
            Pp[r] = Pc[r]; Pc[r] = Pn[r];
            Xp[r] = Xc[r]; Xc[r] = Xn[r];
            Yp[r] = Yc[r]; Yc[r] = Yn[r];
            Cc[r] = Cn[r];
        }
    }
}

extern "C" void kernel_launch(void* const* d_in, const int* in_sizes, int n_in,
                              void* d_out, int out_size) {
    const float* x = (const float*)d_in[0];
    // d_in[1] = kernels (4x3x3x3) — fixed separable stencils folded into the kernel.
    float* out = (float*)d_out;

    dim3 grid(64 / HTB, 64, 64 / ZLEN);  // (8 H tiles, B*C=64, 16 z chunks) = 8192 blocks
    dim3 block(32, 4);                   // 128 threads; warp = two H rows
    perceive3d_kernel<<<grid, block>>>(x, out);
}